// round 7
// baseline (speedup 1.0000x reference)
#include <cuda_runtime.h>
#include <math.h>

#define BB 128
#define TT 512
#define EE 256
#define HH 128
#define VV 32000
#define G4 512   // 4*H
#define KRES 96  // U rows resident in shared memory

// Scratch: xw[dir][t][b][4H]  (time-major input projections), 2*512*128*512 floats = 256 MiB
__device__ float g_xw[(size_t)2 * TT * BB * G4];

__device__ __forceinline__ float sigmoidf_(float x) {
    return 1.0f / (1.0f + expf(-x));
}

// ---------------------------------------------------------------------------
// Kernel 1: fused embedding gather + input projection GEMM.
// C[m, n] = sum_k emb[tok(m)][k] * W_d[k][n%512],  m = t*B + b (one block
// row-tile == one timestep, all 128 batch rows), n in [0,1024) picks direction.
// 128x128 tile, K=256 in steps of 8, 256 threads, 8x8 microtile.
//
// Token dtype is detected at runtime: reference says int64 but JAX without
// x64 emits int32. If int64, all odd 32-bit words are zero high-words
// (tokens < 32000); 32 consecutive zero tokens in int32 data is impossible
// for this dataset, so the check is deterministic.
// ---------------------------------------------------------------------------
__global__ __launch_bounds__(256) void embed_proj_kernel(
    const void* __restrict__ tokens_raw,   // [B, T] int32 or int64
    const float* __restrict__ emb,         // [V, E]
    const float* __restrict__ W_fw,        // [E, 4H]
    const float* __restrict__ W_bw)        // [E, 4H]
{
    __shared__ __align__(16) float As[8][128];
    __shared__ __align__(16) float Bs[8][128];
    __shared__ int srow[128];
    __shared__ int s_is64;

    const int tid = threadIdx.x;
    const int t   = blockIdx.y;            // timestep == m-tile
    const int n0  = blockIdx.x * 128;      // global col in [0,1024)
    const int d   = n0 >> 9;               // direction (whole block same dir)
    const int nn0 = n0 & 511;
    const float* __restrict__ W = d ? W_bw : W_fw;

    if (tid == 0) {
        const int* ti = (const int*)tokens_raw;
        int is64 = 1;
#pragma unroll
        for (int q = 1; q < 64; q += 2) is64 &= (ti[q] == 0);
        s_is64 = is64;
    }
    __syncthreads();
    if (tid < 128) {
        int tok;
        if (s_is64) tok = (int)((const long long*)tokens_raw)[(size_t)tid * TT + t];
        else        tok = ((const int*)tokens_raw)[(size_t)tid * TT + t];
        tok = tok < 0 ? 0 : (tok >= VV ? VV - 1 : tok);  // safety clamp
        srow[tid] = tok;
    }
    __syncthreads();

    const int ry = (tid >> 4) << 3;        // output row base (0..120)
    const int cx = (tid & 15) << 3;        // output col base (0..120)
    const int ai = tid >> 1;               // A-load row (0..127)
    const int ak = (tid & 1) << 2;         // A-load k sub (0 or 4)
    const int bk = tid >> 5;               // B-load k (0..7)
    const int bn = (tid & 31) << 2;        // B-load col (0..124)

    const float* aSrc = emb + (size_t)srow[ai] * EE + ak;
    const float* bSrc = W + (size_t)bk * G4 + nn0 + bn;

    float acc[8][8];
#pragma unroll
    for (int i = 0; i < 8; i++)
#pragma unroll
        for (int j = 0; j < 8; j++) acc[i][j] = 0.0f;

    for (int k0 = 0; k0 < EE; k0 += 8) {
        float4 av = *(const float4*)(aSrc + k0);
        float4 bv = *(const float4*)(bSrc + (size_t)k0 * G4);
        __syncthreads();
        As[ak + 0][ai] = av.x; As[ak + 1][ai] = av.y;
        As[ak + 2][ai] = av.z; As[ak + 3][ai] = av.w;
        *(float4*)&Bs[bk][bn] = bv;
        __syncthreads();
#pragma unroll
        for (int kk = 0; kk < 8; kk++) {
            float a[8], b[8];
            *(float4*)(a)     = *(const float4*)&As[kk][ry];
            *(float4*)(a + 4) = *(const float4*)&As[kk][ry + 4];
            *(float4*)(b)     = *(const float4*)&Bs[kk][cx];
            *(float4*)(b + 4) = *(const float4*)&Bs[kk][cx + 4];
#pragma unroll
            for (int i = 0; i < 8; i++)
#pragma unroll
                for (int j = 0; j < 8; j++)
                    acc[i][j] = fmaf(a[i], b[j], acc[i][j]);
        }
    }

    float* xw = g_xw + (size_t)d * (TT * BB) * G4;
#pragma unroll
    for (int i = 0; i < 8; i++) {
        size_t row = (size_t)t * BB + (ry + i);
        float* dst = xw + row * G4 + (nn0 + cx);
        *(float4*)(dst)     = make_float4(acc[i][0], acc[i][1], acc[i][2], acc[i][3]);
        *(float4*)(dst + 4) = make_float4(acc[i][4], acc[i][5], acc[i][6], acc[i][7]);
    }
}

// ---------------------------------------------------------------------------
// Kernel 2: recurrence. Grid (32, 2): 32 batch-groups (4 rows each) x 2 dirs.
// Blocks are fully independent (state is batch-private) -> no grid sync.
// 96 of 128 U rows live in smem (loaded once), 32 streamed from L2 per step.
// Thread (cg, rsel): cg = 4-wide z-column group, rsel picks 2 of 4 batch rows.
// ---------------------------------------------------------------------------
__global__ __launch_bounds__(256) void lstm_kernel(
    const float* __restrict__ U_fw, const float* __restrict__ bias_fw,
    const float* __restrict__ U_bw, const float* __restrict__ bias_bw,
    float* __restrict__ out, int has_states)
{
    extern __shared__ __align__(16) float smem[];
    float* sh_U = smem;                    // KRES * 512
    float* sh_h = smem + KRES * G4;        // 4 * 128
    float* sh_z = sh_h + 4 * HH;           // 4 * 512

    const int tid = threadIdx.x;
    const int d   = blockIdx.y;
    const int b0  = blockIdx.x * 4;
    const float* __restrict__ U    = d ? U_bw : U_fw;
    const float* __restrict__ bias = d ? bias_bw : bias_fw;

    // Load resident part of U (first 96 rows, contiguous) once.
    for (int q = tid; q < (KRES * G4) / 4; q += 256)
        *(float4*)&sh_U[q * 4] = *(const float4*)&U[q * 4];
    // Zero h state (512 floats)
    sh_h[tid] = 0.0f;
    sh_h[tid + 256] = 0.0f;
    __syncthreads();

    const int cg   = tid & 127;
    const int rsel = tid >> 7;
    const int j4   = cg * 4;
    const int r0   = rsel * 2;
    const int r1   = r0 + 1;

    const float4 bias4 = *(const float4*)&bias[j4];
    float c0 = 0.0f, c1 = 0.0f;

    const float* xwbase = g_xw + (size_t)d * (TT * BB) * G4;
    const int tstart = d ? (TT - 1) : 0;
    const int tinc   = d ? -1 : 1;

    int t = tstart;
    for (int s = 0; s < TT; s++, t += tinc) {
        // z init = xw + bias
        float4 a0 = *(const float4*)&xwbase[((size_t)t * BB + b0 + r0) * G4 + j4];
        float4 a1 = *(const float4*)&xwbase[((size_t)t * BB + b0 + r1) * G4 + j4];
        float acc0[4] = {a0.x + bias4.x, a0.y + bias4.y, a0.z + bias4.z, a0.w + bias4.w};
        float acc1[4] = {a1.x + bias4.x, a1.y + bias4.y, a1.z + bias4.z, a1.w + bias4.w};

        const float* hp0 = sh_h + r0 * HH;
        const float* hp1 = sh_h + r1 * HH;

        // h @ U, resident rows
#pragma unroll 8
        for (int k = 0; k < KRES; k++) {
            float4 u = *(const float4*)&sh_U[(size_t)k * G4 + j4];
            float h0 = hp0[k], h1 = hp1[k];
            acc0[0] = fmaf(h0, u.x, acc0[0]); acc0[1] = fmaf(h0, u.y, acc0[1]);
            acc0[2] = fmaf(h0, u.z, acc0[2]); acc0[3] = fmaf(h0, u.w, acc0[3]);
            acc1[0] = fmaf(h1, u.x, acc1[0]); acc1[1] = fmaf(h1, u.y, acc1[1]);
            acc1[2] = fmaf(h1, u.z, acc1[2]); acc1[3] = fmaf(h1, u.w, acc1[3]);
        }
        // h @ U, streamed rows (L2-resident; coalesced LDG.128 across lanes)
#pragma unroll 8
        for (int k = KRES; k < HH; k++) {
            float4 u = *(const float4*)&U[(size_t)k * G4 + j4];
            float h0 = hp0[k], h1 = hp1[k];
            acc0[0] = fmaf(h0, u.x, acc0[0]); acc0[1] = fmaf(h0, u.y, acc0[1]);
            acc0[2] = fmaf(h0, u.z, acc0[2]); acc0[3] = fmaf(h0, u.w, acc0[3]);
            acc1[0] = fmaf(h1, u.x, acc1[0]); acc1[1] = fmaf(h1, u.y, acc1[1]);
            acc1[2] = fmaf(h1, u.z, acc1[2]); acc1[3] = fmaf(h1, u.w, acc1[3]);
        }

        *(float4*)&sh_z[(size_t)r0 * G4 + j4] = make_float4(acc0[0], acc0[1], acc0[2], acc0[3]);
        *(float4*)&sh_z[(size_t)r1 * G4 + j4] = make_float4(acc1[0], acc1[1], acc1[2], acc1[3]);
        __syncthreads();  // z complete; also orders old-h reads before new-h writes

        // Elementwise gates: thread handles (r0, jh) and (r1, jh), jh = cg
        {
            const int jh = cg;
            {
                float zi = sh_z[r0 * G4 + jh];
                float zf = sh_z[r0 * G4 + 128 + jh];
                float zg = sh_z[r0 * G4 + 256 + jh];
                float zo = sh_z[r0 * G4 + 384 + jh];
                float ig = sigmoidf_(zi), fg = sigmoidf_(zf);
                float gg = tanhf(zg), og = sigmoidf_(zo);
                c0 = fg * c0 + ig * gg;
                float h = og * tanhf(c0);
                sh_h[r0 * HH + jh] = h;
                out[((size_t)(b0 + r0) * TT + t) * 256 + d * 128 + jh] = h;
            }
            {
                float zi = sh_z[r1 * G4 + jh];
                float zf = sh_z[r1 * G4 + 128 + jh];
                float zg = sh_z[r1 * G4 + 256 + jh];
                float zo = sh_z[r1 * G4 + 384 + jh];
                float ig = sigmoidf_(zi), fg = sigmoidf_(zf);
                float gg = tanhf(zg), og = sigmoidf_(zo);
                c1 = fg * c1 + ig * gg;
                float h = og * tanhf(c1);
                sh_h[r1 * HH + jh] = h;
                out[((size_t)(b0 + r1) * TT + t) * 256 + d * 128 + jh] = h;
            }
        }
        __syncthreads();  // new h visible before next step's dot phase
    }

    // Final states: layout out_tail = [h_fw, c_fw, h_bw, c_bw], each [B, H]
    if (has_states) {
        float* st = out + (size_t)BB * TT * 256 + (size_t)d * 2 * BB * HH;
        const int jh = cg;
        st[(b0 + r0) * HH + jh] = sh_h[r0 * HH + jh];
        st[(size_t)BB * HH + (b0 + r0) * HH + jh] = c0;
        st[(b0 + r1) * HH + jh] = sh_h[r1 * HH + jh];
        st[(size_t)BB * HH + (b0 + r1) * HH + jh] = c1;
    }
}

// ---------------------------------------------------------------------------
extern "C" void kernel_launch(void* const* d_in, const int* in_sizes, int n_in,
                              void* d_out, int out_size)
{
    const void*  tokens = d_in[0];
    const float* emb  = (const float*)d_in[1];
    const float* W_fw = (const float*)d_in[2];
    const float* U_fw = (const float*)d_in[3];
    const float* b_fw = (const float*)d_in[4];
    const float* W_bw = (const float*)d_in[5];
    const float* U_bw = (const float*)d_in[6];
    const float* b_bw = (const float*)d_in[7];
    float* out = (float*)d_out;

    // Kernel 1: xw = embed(tokens) @ [W_fw | W_bw]
    dim3 g1(8, 512);
    embed_proj_kernel<<<g1, 256>>>(tokens, emb, W_fw, W_bw);

    // Kernel 2: bidirectional recurrence (needs 207 KB dynamic smem)
    const int smem_bytes = (KRES * G4 + 4 * HH + 4 * G4) * (int)sizeof(float); // 206848
    cudaFuncSetAttribute((const void*)lstm_kernel,
                         cudaFuncAttributeMaxDynamicSharedMemorySize, smem_bytes);
    const long long full = (long long)BB * TT * 256 + 4LL * BB * HH;
    int has_states = ((long long)out_size >= full) ? 1 : 0;
    dim3 g2(32, 2);
    lstm_kernel<<<g2, 256, smem_bytes>>>(U_fw, b_fw, U_bw, b_bw, out, has_states);
}

// round 9
// speedup vs baseline: 1.7642x; 1.7642x over previous
#include <cuda_runtime.h>
#include <math.h>

#define BB 128
#define TT 512
#define EE 256
#define HH 128
#define VV 32000
#define G4 512    // 4*H
#define KRES 108  // U rows resident in shared memory (108*2048 B = 221184 B)

// Scratch: xw[dir][t][b][4H]  (time-major input projections), 2*512*128*512 floats = 256 MiB
__device__ float g_xw[(size_t)2 * TT * BB * G4];

__device__ __forceinline__ float sigmoidf_(float x) {
    return 1.0f / (1.0f + expf(-x));
}

// ---------------------------------------------------------------------------
// Kernel 1: fused embedding gather + input projection GEMM.
// C[m, n] = sum_k emb[tok(m)][k] * W_d[k][n%512],  m = t*B + b (one block
// row-tile == one timestep, all 128 batch rows), n in [0,1024) picks direction.
// 128x128 tile, K=256 in steps of 8, 256 threads, 8x8 microtile.
// Near fp32-FFMA roofline already (~0.8 ms).
// ---------------------------------------------------------------------------
__global__ __launch_bounds__(256) void embed_proj_kernel(
    const void* __restrict__ tokens_raw,   // [B, T] int32 or int64
    const float* __restrict__ emb,         // [V, E]
    const float* __restrict__ W_fw,        // [E, 4H]
    const float* __restrict__ W_bw)        // [E, 4H]
{
    __shared__ __align__(16) float As[8][128];
    __shared__ __align__(16) float Bs[8][128];
    __shared__ int srow[128];
    __shared__ int s_is64;

    const int tid = threadIdx.x;
    const int t   = blockIdx.y;            // timestep == m-tile
    const int n0  = blockIdx.x * 128;      // global col in [0,1024)
    const int d   = n0 >> 9;               // direction (whole block same dir)
    const int nn0 = n0 & 511;
    const float* __restrict__ W = d ? W_bw : W_fw;

    if (tid == 0) {
        const int* ti = (const int*)tokens_raw;
        int is64 = 1;
#pragma unroll
        for (int q = 1; q < 64; q += 2) is64 &= (ti[q] == 0);
        s_is64 = is64;
    }
    __syncthreads();
    if (tid < 128) {
        int tok;
        if (s_is64) tok = (int)((const long long*)tokens_raw)[(size_t)tid * TT + t];
        else        tok = ((const int*)tokens_raw)[(size_t)tid * TT + t];
        tok = tok < 0 ? 0 : (tok >= VV ? VV - 1 : tok);  // safety clamp
        srow[tid] = tok;
    }
    __syncthreads();

    const int ry = (tid >> 4) << 3;        // output row base (0..120)
    const int cx = (tid & 15) << 3;        // output col base (0..120)
    const int ai = tid >> 1;               // A-load row (0..127)
    const int ak = (tid & 1) << 2;         // A-load k sub (0 or 4)
    const int bk = tid >> 5;               // B-load k (0..7)
    const int bn = (tid & 31) << 2;        // B-load col (0..124)

    const float* aSrc = emb + (size_t)srow[ai] * EE + ak;
    const float* bSrc = W + (size_t)bk * G4 + nn0 + bn;

    float acc[8][8];
#pragma unroll
    for (int i = 0; i < 8; i++)
#pragma unroll
        for (int j = 0; j < 8; j++) acc[i][j] = 0.0f;

    for (int k0 = 0; k0 < EE; k0 += 8) {
        float4 av = *(const float4*)(aSrc + k0);
        float4 bv = *(const float4*)(bSrc + (size_t)k0 * G4);
        __syncthreads();
        As[ak + 0][ai] = av.x; As[ak + 1][ai] = av.y;
        As[ak + 2][ai] = av.z; As[ak + 3][ai] = av.w;
        *(float4*)&Bs[bk][bn] = bv;
        __syncthreads();
#pragma unroll
        for (int kk = 0; kk < 8; kk++) {
            float a[8], b[8];
            *(float4*)(a)     = *(const float4*)&As[kk][ry];
            *(float4*)(a + 4) = *(const float4*)&As[kk][ry + 4];
            *(float4*)(b)     = *(const float4*)&Bs[kk][cx];
            *(float4*)(b + 4) = *(const float4*)&Bs[kk][cx + 4];
#pragma unroll
            for (int i = 0; i < 8; i++)
#pragma unroll
                for (int j = 0; j < 8; j++)
                    acc[i][j] = fmaf(a[i], b[j], acc[i][j]);
        }
    }

    float* xw = g_xw + (size_t)d * (TT * BB) * G4;
#pragma unroll
    for (int i = 0; i < 8; i++) {
        size_t row = (size_t)t * BB + (ry + i);
        float* dst = xw + row * G4 + (nn0 + cx);
        *(float4*)(dst)     = make_float4(acc[i][0], acc[i][1], acc[i][2], acc[i][3]);
        *(float4*)(dst + 4) = make_float4(acc[i][4], acc[i][5], acc[i][6], acc[i][7]);
    }
}

// ---------------------------------------------------------------------------
// Kernel 2: recurrence. Grid (64, 2): 64 batch-groups (2 rows each) x 2 dirs
// = 128 independent blocks (one per SM, no inter-block sync).
// 512 threads: thread j owns z-column j for BOTH batch rows (u loaded once,
// used twice). 108/128 U rows resident in smem; 20 streamed from L2.
// h is block-uniform -> broadcast float4 LDS (near-free crossbar).
// ---------------------------------------------------------------------------
__global__ __launch_bounds__(512) void lstm_kernel(
    const float* __restrict__ U_fw, const float* __restrict__ bias_fw,
    const float* __restrict__ U_bw, const float* __restrict__ bias_bw,
    float* __restrict__ out, int has_states)
{
    extern __shared__ __align__(16) float smem[];
    float* sh_U = smem;                    // KRES * 512
    float* sh_h = smem + KRES * G4;        // 2 * 128
    float* sh_z = sh_h + 2 * HH;           // 2 * 512

    const int tid = threadIdx.x;
    const int d   = blockIdx.y;
    const int b0  = blockIdx.x * 2;
    const float* __restrict__ U    = d ? U_bw : U_fw;
    const float* __restrict__ bias = d ? bias_bw : bias_fw;

    // Load resident part of U (first KRES rows, contiguous) once.
    for (int q = tid; q < (KRES * G4) / 4; q += 512)
        *(float4*)&sh_U[q * 4] = *(const float4*)&U[q * 4];
    // Zero h state (256 floats)
    if (tid < 2 * HH) sh_h[tid] = 0.0f;
    __syncthreads();

    const int j = tid;                     // z column (0..511)
    const float bias_j = bias[j];

    // Gate-phase mapping: threads 0..255 -> (row, jh)
    const int grow = tid >> 7;             // 0 or 1
    const int gjh  = tid & 127;
    float cst = 0.0f;                      // c state (valid for tid < 256)

    const float* xwbase = g_xw + (size_t)d * (TT * BB) * G4;
    const int tstart = d ? (TT - 1) : 0;
    const int tinc   = d ? -1 : 1;

    int t = tstart;
    for (int s = 0; s < TT; s++, t += tinc) {
        // xw loads issued first; consumed after the k-loop (latency hidden)
        const float xa0 = xwbase[((size_t)t * BB + b0 + 0) * G4 + j];
        const float xa1 = xwbase[((size_t)t * BB + b0 + 1) * G4 + j];
        float acc0 = bias_j;
        float acc1 = bias_j;

        // h @ U, resident rows (u: conflict-free LDS.32; h: uniform broadcast)
#pragma unroll 9
        for (int k0 = 0; k0 < KRES; k0 += 4) {
            float4 h0 = *(const float4*)&sh_h[k0];
            float4 h1 = *(const float4*)&sh_h[HH + k0];
            float u0 = sh_U[(size_t)(k0 + 0) * G4 + j];
            float u1 = sh_U[(size_t)(k0 + 1) * G4 + j];
            float u2 = sh_U[(size_t)(k0 + 2) * G4 + j];
            float u3 = sh_U[(size_t)(k0 + 3) * G4 + j];
            acc0 = fmaf(h0.x, u0, acc0); acc1 = fmaf(h1.x, u0, acc1);
            acc0 = fmaf(h0.y, u1, acc0); acc1 = fmaf(h1.y, u1, acc1);
            acc0 = fmaf(h0.z, u2, acc0); acc1 = fmaf(h1.z, u2, acc1);
            acc0 = fmaf(h0.w, u3, acc0); acc1 = fmaf(h1.w, u3, acc1);
        }
        // h @ U, streamed rows (L2-resident, coalesced LDG across lanes)
#pragma unroll
        for (int k0 = KRES; k0 < HH; k0 += 4) {
            float4 h0 = *(const float4*)&sh_h[k0];
            float4 h1 = *(const float4*)&sh_h[HH + k0];
            float u0 = U[(size_t)(k0 + 0) * G4 + j];
            float u1 = U[(size_t)(k0 + 1) * G4 + j];
            float u2 = U[(size_t)(k0 + 2) * G4 + j];
            float u3 = U[(size_t)(k0 + 3) * G4 + j];
            acc0 = fmaf(h0.x, u0, acc0); acc1 = fmaf(h1.x, u0, acc1);
            acc0 = fmaf(h0.y, u1, acc0); acc1 = fmaf(h1.y, u1, acc1);
            acc0 = fmaf(h0.z, u2, acc0); acc1 = fmaf(h1.z, u2, acc1);
            acc0 = fmaf(h0.w, u3, acc0); acc1 = fmaf(h1.w, u3, acc1);
        }

        sh_z[j]      = acc0 + xa0;
        sh_z[G4 + j] = acc1 + xa1;
        __syncthreads();  // z complete; also orders old-h reads before new-h writes

        // Elementwise gates: threads 0..255, thread -> (grow, gjh)
        if (tid < 256) {
            const float* zr = sh_z + grow * G4;
            float zi = zr[gjh];
            float zf = zr[128 + gjh];
            float zg = zr[256 + gjh];
            float zo = zr[384 + gjh];
            float ig = sigmoidf_(zi), fg = sigmoidf_(zf);
            float gg = tanhf(zg),     og = sigmoidf_(zo);
            cst = fg * cst + ig * gg;
            float h = og * tanhf(cst);
            sh_h[grow * HH + gjh] = h;
            out[((size_t)(b0 + grow) * TT + t) * 256 + d * 128 + gjh] = h;
        }
        __syncthreads();  // new h visible before next step's dot phase
    }

    // Final states: layout out_tail = [h_fw, c_fw, h_bw, c_bw], each [B, H]
    if (has_states && tid < 256) {
        float* st = out + (size_t)BB * TT * 256 + (size_t)d * 2 * BB * HH;
        st[(b0 + grow) * HH + gjh] = sh_h[grow * HH + gjh];
        st[(size_t)BB * HH + (b0 + grow) * HH + gjh] = cst;
    }
}

// ---------------------------------------------------------------------------
extern "C" void kernel_launch(void* const* d_in, const int* in_sizes, int n_in,
                              void* d_out, int out_size)
{
    const void*  tokens = d_in[0];
    const float* emb  = (const float*)d_in[1];
    const float* W_fw = (const float*)d_in[2];
    const float* U_fw = (const float*)d_in[3];
    const float* b_fw = (const float*)d_in[4];
    const float* W_bw = (const float*)d_in[5];
    const float* U_bw = (const float*)d_in[6];
    const float* b_bw = (const float*)d_in[7];
    float* out = (float*)d_out;

    // Kernel 1: xw = embed(tokens) @ [W_fw | W_bw]
    dim3 g1(8, 512);
    embed_proj_kernel<<<g1, 256>>>(tokens, emb, W_fw, W_bw);

    // Kernel 2: bidirectional recurrence (226304 B dynamic smem)
    const int smem_bytes = (KRES * G4 + 2 * HH + 2 * G4) * (int)sizeof(float);
    cudaFuncSetAttribute((const void*)lstm_kernel,
                         cudaFuncAttributeMaxDynamicSharedMemorySize, smem_bytes);
    const long long full = (long long)BB * TT * 256 + 4LL * BB * HH;
    int has_states = ((long long)out_size >= full) ? 1 : 0;
    dim3 g2(64, 2);
    lstm_kernel<<<g2, 512, smem_bytes>>>(U_fw, b_fw, U_bw, b_bw, out, has_states);
}